// round 8
// baseline (speedup 1.0000x reference)
#include <cuda_runtime.h>

// EdgesToGlobalsAggregator: segment-sum of edges [TOTAL_EDGES, 128] fp32 into
// [num_graphs, 128] fp32. Fused single kernel: each block computes its own
// exclusive prefix of n_edge (4KB, L2-resident), then streams its segment.
// R7: champion R2 layout + 8-deep LDG.128 pipeline per warp (MLP 4 -> 8) to
// hold DRAM saturation through wave ramp/drain. __ldcs kept (R6 showed no-ldcs
// is not better). Reg budget ~58, fits occ-4 / 64-reg envelope.

#define D_FEAT 128
#define VEC (D_FEAT / 4)   // 32 float4 per row
#define NTHREADS 256

__global__ __launch_bounds__(NTHREADS, 4)
void segment_sum_fused_kernel(const float4* __restrict__ edges,
                              const int* __restrict__ n_edge,
                              int num_graphs,
                              float4* __restrict__ out) {
    const int g    = blockIdx.x;
    const int tid  = threadIdx.x;
    const int lane = tid & 31;   // float4 feature slot 0..31
    const int warp = tid >> 5;   // row-slice 0..7

    // ---- per-block exclusive prefix: start = sum(n_edge[0..g-1]), mine = n_edge[g]
    __shared__ int s_warp[8];
    __shared__ int s_start, s_mine;

    int local = 0;
    for (int i = tid; i < g; i += NTHREADS)
        local += __ldg(&n_edge[i]);
    #pragma unroll
    for (int off = 16; off > 0; off >>= 1)
        local += __shfl_down_sync(0xFFFFFFFFu, local, off);
    if (lane == 0) s_warp[warp] = local;
    __syncthreads();
    if (tid == 0) {
        int acc = 0;
        #pragma unroll
        for (int i = 0; i < 8; i++) acc += s_warp[i];
        s_start = acc;
        s_mine  = __ldg(&n_edge[g]);
    }
    __syncthreads();

    const int start = s_start;
    const int nrows = s_mine;

    const float4* __restrict__ base = edges + (size_t)start * VEC;

    float4 a0 = make_float4(0.f, 0.f, 0.f, 0.f);
    float4 a1 = make_float4(0.f, 0.f, 0.f, 0.f);
    float4 a2 = make_float4(0.f, 0.f, 0.f, 0.f);
    float4 a3 = make_float4(0.f, 0.f, 0.f, 0.f);

    int r = warp;
    // 8-way unrolled main loop: 8 independent streaming LDG.128 in flight.
    for (; r + 56 < nrows; r += 64) {
        float4 v0 = __ldcs(&base[(size_t)(r)      * VEC + lane]);
        float4 v1 = __ldcs(&base[(size_t)(r + 8)  * VEC + lane]);
        float4 v2 = __ldcs(&base[(size_t)(r + 16) * VEC + lane]);
        float4 v3 = __ldcs(&base[(size_t)(r + 24) * VEC + lane]);
        float4 v4 = __ldcs(&base[(size_t)(r + 32) * VEC + lane]);
        float4 v5 = __ldcs(&base[(size_t)(r + 40) * VEC + lane]);
        float4 v6 = __ldcs(&base[(size_t)(r + 48) * VEC + lane]);
        float4 v7 = __ldcs(&base[(size_t)(r + 56) * VEC + lane]);
        a0.x += v0.x; a0.y += v0.y; a0.z += v0.z; a0.w += v0.w;
        a1.x += v1.x; a1.y += v1.y; a1.z += v1.z; a1.w += v1.w;
        a2.x += v2.x; a2.y += v2.y; a2.z += v2.z; a2.w += v2.w;
        a3.x += v3.x; a3.y += v3.y; a3.z += v3.z; a3.w += v3.w;
        a0.x += v4.x; a0.y += v4.y; a0.z += v4.z; a0.w += v4.w;
        a1.x += v5.x; a1.y += v5.y; a1.z += v5.z; a1.w += v5.w;
        a2.x += v6.x; a2.y += v6.y; a2.z += v6.z; a2.w += v6.w;
        a3.x += v7.x; a3.y += v7.y; a3.z += v7.z; a3.w += v7.w;
    }
    // 4-way tail
    for (; r + 24 < nrows; r += 32) {
        float4 v0 = __ldcs(&base[(size_t)(r)      * VEC + lane]);
        float4 v1 = __ldcs(&base[(size_t)(r + 8)  * VEC + lane]);
        float4 v2 = __ldcs(&base[(size_t)(r + 16) * VEC + lane]);
        float4 v3 = __ldcs(&base[(size_t)(r + 24) * VEC + lane]);
        a0.x += v0.x; a0.y += v0.y; a0.z += v0.z; a0.w += v0.w;
        a1.x += v1.x; a1.y += v1.y; a1.z += v1.z; a1.w += v1.w;
        a2.x += v2.x; a2.y += v2.y; a2.z += v2.z; a2.w += v2.w;
        a3.x += v3.x; a3.y += v3.y; a3.z += v3.z; a3.w += v3.w;
    }
    // scalar tail
    for (; r < nrows; r += 8) {
        float4 v = __ldcs(&base[(size_t)r * VEC + lane]);
        a0.x += v.x; a0.y += v.y; a0.z += v.z; a0.w += v.w;
    }

    a0.x += a1.x + a2.x + a3.x;
    a0.y += a1.y + a2.y + a3.y;
    a0.z += a1.z + a2.z + a3.z;
    a0.w += a1.w + a2.w + a3.w;

    __shared__ float4 sp[8][32];
    sp[warp][lane] = a0;
    __syncthreads();

    if (warp == 0) {
        float4 s = sp[0][lane];
        #pragma unroll
        for (int i = 1; i < 8; i++) {
            float4 v = sp[i][lane];
            s.x += v.x; s.y += v.y; s.z += v.z; s.w += v.w;
        }
        out[(size_t)g * VEC + lane] = s;
    }
}

extern "C" void kernel_launch(void* const* d_in, const int* in_sizes, int n_in,
                              void* d_out, int out_size) {
    const float* edges  = (const float*)d_in[0];
    const int*   n_edge = (const int*)d_in[1];
    const int num_graphs = in_sizes[1];          // 1024

    segment_sum_fused_kernel<<<num_graphs, NTHREADS>>>(
        (const float4*)edges, n_edge, num_graphs, (float4*)d_out);
}